// round 3
// baseline (speedup 1.0000x reference)
#include <cuda_runtime.h>

#define Bc 8
#define Cc 96
#define Hc 256
#define Wc 256
#define TH 32                   // output rows per block
#define RROWS 40                // raw rows in smem (TH + 2*4 halo)
#define NQ 66                   // float4 quads per smem row (cols -4..259)
#define QS 67                   // quad row stride

// reciprocal of valid-count for avgpool (count_include_pad=False), 0 if index outside image
__device__ __forceinline__ float rcnt0(int i, int p) {
    if (i < 0 || i > Hc - 1) return 0.f;
    int lo = i - p; if (lo < 0) lo = 0;
    int hi = i + p; if (hi > Hc - 1) hi = Hc - 1;
    return __fdividef(1.f, (float)(hi - lo + 1));
}

__device__ __forceinline__ float bn_silu(float acc, float scal, float shft) {
    float v = fmaf(acc, scal, shft);
    return v * __fdividef(1.f, 1.f + __expf(-v));
}

// load 3 consecutive quads (12 floats) from smem
__device__ __forceinline__ void ld12(const float4* __restrict__ p, float* __restrict__ d) {
    float4 A = p[0], B = p[1], C = p[2];
    d[0]=A.x; d[1]=A.y; d[2]=A.z;  d[3]=A.w;
    d[4]=B.x; d[5]=B.y; d[6]=B.z;  d[7]=B.w;
    d[8]=C.x; d[9]=C.y; d[10]=C.z; d[11]=C.w;
}

__global__ __launch_bounds__(256) void trifreq_kernel(
    const float* __restrict__ x,
    const float* __restrict__ w_lo,
    const float* __restrict__ w_mf,
    const float* __restrict__ w_hf,
    const float* __restrict__ bn_gamma,
    const float* __restrict__ bn_beta,
    const float* __restrict__ bn_mean,
    const float* __restrict__ bn_var,
    float* __restrict__ out)
{
    __shared__ float4 s_raw[RROWS * QS];
    __shared__ float s_w[25];

    const int t = threadIdx.x;
    const int tileY = blockIdx.x;
    const int ch = blockIdx.y;
    const int b = blockIdx.z;
    const int group = ch >> 5;   // 0=lo, 1=mf, 2=hf
    const int k = ch & 31;
    const int rowBase = tileY * TH;

    if (group == 0)      { if (t < 25) s_w[t] = w_lo[k * 25 + t]; }
    else if (group == 1) { if (t < 9)  s_w[t] = w_mf[k * 9 + t]; }
    else                 { if (t < 9)  s_w[t] = w_hf[k * 9 + t]; }

    // ---- cooperative raw tile load (zero outside image) ----
    const float* xp = x + (size_t)(b * Cc + ch) * Hc * Wc;
    const int rlo = (group == 0) ? 2 : 0;     // lo only needs halo 2
    const int rhi = (group == 0) ? 38 : 40;
    const int nload = (rhi - rlo) * NQ;
    for (int idx = t; idx < nload; idx += 256) {
        int rr = idx / NQ + rlo;
        int q = idx - (rr - rlo) * NQ;
        int gr = rowBase + rr - 4;
        float4 v = make_float4(0.f, 0.f, 0.f, 0.f);
        if (q >= 1 && q <= 64 && (unsigned)gr < (unsigned)Hc)
            v = *(const float4*)(xp + gr * Wc + (q - 1) * 4);
        s_raw[rr * QS + q] = v;
    }
    __syncthreads();

    const int oc = 3 * k + group;                // channel shuffle folded in
    const float inv  = bn_gamma[oc] * rsqrtf(bn_var[oc] + 1e-5f);
    const float shft = bn_beta[oc] - bn_mean[oc] * inv;

    const int j = t & 63;          // quad: output cols 4j..4j+3
    const int rc = t >> 6;         // row band
    const int gy0 = rowBase + rc * 8;
    float* outp = out + (size_t)(b * Cc + oc) * Hc * Wc + j * 4;
    // smem row for global row g is (g - rowBase + 4); quads j..j+2
    const float4* qb = s_raw + j;
#define RQ(g) (qb + ((g) - rowBase + 4) * QS)

    if (group == 0) {
        // ================= lo: 5x5 dwconv, rolling 5x12 register window =================
        float w[25];
#pragma unroll
        for (int i = 0; i < 25; i++) w[i] = s_w[i];
        float win[5][12];
#pragma unroll
        for (int r = 0; r < 4; r++) ld12(RQ(gy0 - 2 + r), win[r]);  // rows gy0-2..gy0+1
#pragma unroll
        for (int i = 0; i < 8; i++) {
            int gy = gy0 + i;
            ld12(RQ(gy + 2), win[(i + 4) % 5]);
            float a0 = 0.f, a1 = 0.f, a2 = 0.f, a3 = 0.f;
#pragma unroll
            for (int kr = 0; kr < 5; kr++) {
                const float* rr = win[(i + kr) % 5];   // row gy-2+kr
#pragma unroll
                for (int kc = 0; kc < 5; kc++) {
                    float wv = w[kr * 5 + kc];
                    a0 = fmaf(wv, rr[2 + kc], a0);
                    a1 = fmaf(wv, rr[3 + kc], a1);
                    a2 = fmaf(wv, rr[4 + kc], a2);
                    a3 = fmaf(wv, rr[5 + kc], a3);
                }
            }
            float4 o;
            o.x = bn_silu(a0, inv, shft); o.y = bn_silu(a1, inv, shft);
            o.z = bn_silu(a2, inv, shft); o.w = bn_silu(a3, inv, shft);
            *(float4*)(outp + (size_t)gy * Wc) = o;
        }
        return;
    }

    // horizontal count reciprocals for cols 4j-1..4j+4 (0 if col outside image)
    float icx3[6];
#pragma unroll
    for (int u = 0; u < 6; u++) icx3[u] = rcnt0(4 * j - 1 + u, 1);

    float w[9];
#pragma unroll
    for (int i = 0; i < 9; i++) w[i] = s_w[i];

    if (group == 1) {
        // ================= mf: (avg3-avg7) band-pass + 3x3 dwconv, all in registers =================
        float icx7[6];
#pragma unroll
        for (int u = 0; u < 6; u++) icx7[u] = rcnt0(4 * j - 1 + u, 3);

        float v3[12], v7[12], tmp[12];
#pragma unroll
        for (int z = 0; z < 12; z++) { v3[z] = 0.f; v7[z] = 0.f; }
        // prime vertical sums for bp row g0 = gy0-1: v3 rows gy0-2..gy0, v7 rows gy0-4..gy0+2
#pragma unroll
        for (int dr = -4; dr <= 2; dr++) {
            ld12(RQ(gy0 + dr), tmp);
#pragma unroll
            for (int z = 0; z < 12; z++) {
                v7[z] += tmp[z];
                if (dr >= -2 && dr <= 0) v3[z] += tmp[z];
            }
        }

        float bpw[3][6];
        // bp row builder: uses current v3/v7 (must correspond to row g)
#define MKBP(g, dst) do {                                                    \
            float iy3 = rcnt0((g), 1), iy7 = rcnt0((g), 3);                  \
            float h3[6], h7[6];                                              \
            h3[0] = v3[2] + v3[3] + v3[4];                                   \
            _Pragma("unroll")                                                \
            for (int u = 1; u < 6; u++) h3[u] = h3[u-1] + v3[u+4] - v3[u+1]; \
            h7[0] = v7[0]+v7[1]+v7[2]+v7[3]+v7[4]+v7[5]+v7[6];               \
            _Pragma("unroll")                                                \
            for (int u = 1; u < 6; u++) h7[u] = h7[u-1] + v7[u+6] - v7[u-1]; \
            _Pragma("unroll")                                                \
            for (int u = 0; u < 6; u++)                                      \
                (dst)[u] = h3[u] * (icx3[u] * iy3) - h7[u] * (icx7[u] * iy7);\
        } while (0)
#define ADV3(g) do { float t1[12], t2[12];                                   \
            ld12(RQ((g) + 2), t1); ld12(RQ((g) - 1), t2);                    \
            _Pragma("unroll")                                                \
            for (int z = 0; z < 12; z++) v3[z] += t1[z] - t2[z]; } while (0)
#define ADV7(g) do { float t1[12], t2[12];                                   \
            ld12(RQ((g) + 4), t1); ld12(RQ((g) - 3), t2);                    \
            _Pragma("unroll")                                                \
            for (int z = 0; z < 12; z++) v7[z] += t1[z] - t2[z]; } while (0)

        MKBP(gy0 - 1, bpw[0]);
        ADV3(gy0 - 1); ADV7(gy0 - 1);          // advance sums to row gy0
        MKBP(gy0, bpw[1]);
#pragma unroll
        for (int i = 0; i < 8; i++) {
            int gy = gy0 + i;
            ADV3(gy); ADV7(gy);                // advance sums to row gy+1
            MKBP(gy + 1, bpw[(i + 2) % 3]);
            const float *A = bpw[i % 3], *B = bpw[(i + 1) % 3], *C = bpw[(i + 2) % 3];
            float a0 = 0.f, a1 = 0.f, a2 = 0.f, a3 = 0.f;
#pragma unroll
            for (int kc = 0; kc < 3; kc++) {
                float w0 = w[kc], w1 = w[3 + kc], w2 = w[6 + kc];
                a0 = fmaf(w0, A[0 + kc], a0); a0 = fmaf(w1, B[0 + kc], a0); a0 = fmaf(w2, C[0 + kc], a0);
                a1 = fmaf(w0, A[1 + kc], a1); a1 = fmaf(w1, B[1 + kc], a1); a1 = fmaf(w2, C[1 + kc], a1);
                a2 = fmaf(w0, A[2 + kc], a2); a2 = fmaf(w1, B[2 + kc], a2); a2 = fmaf(w2, C[2 + kc], a2);
                a3 = fmaf(w0, A[3 + kc], a3); a3 = fmaf(w1, B[3 + kc], a3); a3 = fmaf(w2, C[3 + kc], a3);
            }
            float4 o;
            o.x = bn_silu(a0, inv, shft); o.y = bn_silu(a1, inv, shft);
            o.z = bn_silu(a2, inv, shft); o.w = bn_silu(a3, inv, shft);
            *(float4*)(outp + (size_t)gy * Wc) = o;
        }
        return;
    }

    // ================= hf: (x - avg3) high-pass + 3x3 dwconv, rolling raw cache =================
    {
        float rr[4][12];                       // raw rows cache; row g -> slot (g-(gy0-2))&3
        float v3[12], hpw[3][6];
#pragma unroll
        for (int r = 0; r < 4; r++) ld12(RQ(gy0 - 2 + r), rr[r]);   // rows gy0-2..gy0+1
#pragma unroll
        for (int z = 0; z < 12; z++) v3[z] = rr[0][z] + rr[1][z] + rr[2][z];  // row gy0-1

#define MKHP(g, rawr, dst) do {                                              \
            float iy3 = rcnt0((g), 1);                                       \
            float h3[6];                                                     \
            h3[0] = v3[2] + v3[3] + v3[4];                                   \
            _Pragma("unroll")                                                \
            for (int u = 1; u < 6; u++) h3[u] = h3[u-1] + v3[u+4] - v3[u+1]; \
            _Pragma("unroll")                                                \
            for (int u = 0; u < 6; u++)                                      \
                (dst)[u] = (rawr)[u + 3] - h3[u] * (icx3[u] * iy3);          \
        } while (0)

        MKHP(gy0 - 1, rr[1], hpw[0]);
#pragma unroll
        for (int z = 0; z < 12; z++) v3[z] += rr[3][z] - rr[0][z];  // -> row gy0
        MKHP(gy0, rr[2], hpw[1]);
#pragma unroll
        for (int i = 0; i < 8; i++) {
            int gy = gy0 + i;
            ld12(RQ(gy + 2), rr[i & 3]);                 // overwrite row gy-2
#pragma unroll
            for (int z = 0; z < 12; z++) v3[z] += rr[i & 3][z] - rr[(i + 1) & 3][z]; // -> row gy+1
            MKHP(gy + 1, rr[(i + 3) & 3], hpw[(i + 2) % 3]);
            const float *A = hpw[i % 3], *B = hpw[(i + 1) % 3], *C = hpw[(i + 2) % 3];
            float a0 = 0.f, a1 = 0.f, a2 = 0.f, a3 = 0.f;
#pragma unroll
            for (int kc = 0; kc < 3; kc++) {
                float w0 = w[kc], w1 = w[3 + kc], w2 = w[6 + kc];
                a0 = fmaf(w0, A[0 + kc], a0); a0 = fmaf(w1, B[0 + kc], a0); a0 = fmaf(w2, C[0 + kc], a0);
                a1 = fmaf(w0, A[1 + kc], a1); a1 = fmaf(w1, B[1 + kc], a1); a1 = fmaf(w2, C[1 + kc], a1);
                a2 = fmaf(w0, A[2 + kc], a2); a2 = fmaf(w1, B[2 + kc], a2); a2 = fmaf(w2, C[2 + kc], a2);
                a3 = fmaf(w0, A[3 + kc], a3); a3 = fmaf(w1, B[3 + kc], a3); a3 = fmaf(w2, C[3 + kc], a3);
            }
            float4 o;
            o.x = bn_silu(a0, inv, shft); o.y = bn_silu(a1, inv, shft);
            o.z = bn_silu(a2, inv, shft); o.w = bn_silu(a3, inv, shft);
            *(float4*)(outp + (size_t)gy * Wc) = o;
        }
    }
}

extern "C" void kernel_launch(void* const* d_in, const int* in_sizes, int n_in,
                              void* d_out, int out_size) {
    (void)in_sizes; (void)n_in; (void)out_size;
    dim3 grid(Hc / TH, Cc, Bc);
    dim3 block(256);
    trifreq_kernel<<<grid, block>>>(
        (const float*)d_in[0], (const float*)d_in[1], (const float*)d_in[2],
        (const float*)d_in[3], (const float*)d_in[4], (const float*)d_in[5],
        (const float*)d_in[6], (const float*)d_in[7], (float*)d_out);
}

// round 4
// speedup vs baseline: 1.8493x; 1.8493x over previous
#include <cuda_runtime.h>

#define Bc 8
#define Cc 96
#define Hc 256
#define Wc 256
#define TH 16                   // output rows per block
#define RROWS 24                // raw rows (TH + 2*4)
#define VRS 18                  // vertical-sum / bp rows (TH + 2)
#define NQ 66                   // float4 quads per row (cols -4..259)
#define QS 67                   // quad row stride
#define SMEM_BYTES ((RROWS + 2 * VRS) * QS * 16)   // 64320

__device__ __forceinline__ float4 f4add(float4 a, float4 b) {
    return make_float4(a.x+b.x, a.y+b.y, a.z+b.z, a.w+b.w);
}
__device__ __forceinline__ float4 f4sub(float4 a, float4 b) {
    return make_float4(a.x-b.x, a.y-b.y, a.z-b.z, a.w-b.w);
}

// reciprocal of valid-count for avgpool (count_include_pad=False); 0 outside image
__device__ __forceinline__ float rcnt0(int i, int p) {
    if (i < 0 || i > Hc - 1) return 0.f;
    int lo = i - p; if (lo < 0) lo = 0;
    int hi = i + p; if (hi > Hc - 1) hi = Hc - 1;
    return __fdividef(1.f, (float)(hi - lo + 1));
}

__device__ __forceinline__ float bn_silu(float acc, float scal, float shft) {
    float v = fmaf(acc, scal, shft);
    return v * __fdividef(1.f, 1.f + __expf(-v));
}

__device__ __forceinline__ void ld12(const float4* __restrict__ p, float* __restrict__ d) {
    float4 A = p[0], B = p[1], C = p[2];
    d[0]=A.x; d[1]=A.y; d[2]=A.z;  d[3]=A.w;
    d[4]=B.x; d[5]=B.y; d[6]=B.z;  d[7]=B.w;
    d[8]=C.x; d[9]=C.y; d[10]=C.z; d[11]=C.w;
}

// 3x3 conv: read 6 buffer rows once each, scatter into 4 adjacent row accumulators
__device__ __forceinline__ void conv3_scatter(const float4* __restrict__ bufj,
                                              int baseSlot,
                                              const float* __restrict__ w,
                                              float inv, float shft,
                                              float* __restrict__ outp, int gy0) {
    float acc[4][4];
#pragma unroll
    for (int o = 0; o < 4; o++)
#pragma unroll
        for (int p = 0; p < 4; p++) acc[o][p] = 0.f;
#pragma unroll
    for (int rrow = 0; rrow < 6; rrow++) {
        float c[12];
        ld12(bufj + (baseSlot + rrow) * QS, c);
#pragma unroll
        for (int o = 0; o < 4; o++) {
            int kr = rrow - o;
            if (kr >= 0 && kr < 3) {
#pragma unroll
                for (int kc = 0; kc < 3; kc++) {
                    float wv = w[kr * 3 + kc];
#pragma unroll
                    for (int p = 0; p < 4; p++)
                        acc[o][p] = fmaf(wv, c[p + 3 + kc], acc[o][p]);
                }
            }
        }
    }
#pragma unroll
    for (int o = 0; o < 4; o++) {
        float4 ov;
        ov.x = bn_silu(acc[o][0], inv, shft);
        ov.y = bn_silu(acc[o][1], inv, shft);
        ov.z = bn_silu(acc[o][2], inv, shft);
        ov.w = bn_silu(acc[o][3], inv, shft);
        *(float4*)(outp + (size_t)(gy0 + o) * Wc) = ov;
    }
}

__global__ __launch_bounds__(256, 3) void trifreq_kernel(
    const float* __restrict__ x,
    const float* __restrict__ w_lo,
    const float* __restrict__ w_mf,
    const float* __restrict__ w_hf,
    const float* __restrict__ bn_gamma,
    const float* __restrict__ bn_beta,
    const float* __restrict__ bn_mean,
    const float* __restrict__ bn_var,
    float* __restrict__ out)
{
    extern __shared__ float4 sm[];
    float4* s_raw = sm;                      // 24 rows: raw; mf reuses rows 0..17 for bp
    float4* s_a   = sm + RROWS * QS;         // 18 rows: vertical 3-sums
    float4* s_b   = s_a + VRS * QS;          // 18 rows: vertical 7-sums (hf: high-pass)
    __shared__ float s_w[25];

    const int t = threadIdx.x;
    const int tileY = blockIdx.x;
    const int ch = blockIdx.y;
    const int b = blockIdx.z;
    const int group = ch >> 5;   // 0=lo, 1=mf, 2=hf
    const int k = ch & 31;
    const int rowBase = tileY * TH;

    if (group == 0)      { if (t < 25) s_w[t] = w_lo[k * 25 + t]; }
    else if (group == 1) { if (t < 9)  s_w[t] = w_mf[k * 9 + t]; }
    else                 { if (t < 9)  s_w[t] = w_hf[k * 9 + t]; }

    // ---- cooperative raw tile load (zero outside image) ----
    const float* xp = x + (size_t)(b * Cc + ch) * Hc * Wc;
    const int rlo = (group == 0) ? 2 : 0;
    const int rhi = (group == 0) ? 22 : 24;
    const int nload = (rhi - rlo) * NQ;
    for (int idx = t; idx < nload; idx += 256) {
        int rr = idx / NQ + rlo;
        int q = idx - (rr - rlo) * NQ;
        int gr = rowBase + rr - 4;
        float4 v = make_float4(0.f, 0.f, 0.f, 0.f);
        if (q >= 1 && q <= 64 && (unsigned)gr < (unsigned)Hc)
            v = *(const float4*)(xp + gr * Wc + (q - 1) * 4);
        s_raw[rr * QS + q] = v;
    }
    __syncthreads();

    const int oc = 3 * k + group;                // channel shuffle folded in
    const float inv  = bn_gamma[oc] * rsqrtf(bn_var[oc] + 1e-5f);
    const float shft = bn_beta[oc] - bn_mean[oc] * inv;

    const int j = t & 63;          // quad: output cols 4j..4j+3
    const int rc = t >> 6;         // band: 4 adjacent rows
    const int gy0 = rowBase + rc * 4;
    float* outp = out + (size_t)(b * Cc + oc) * Hc * Wc + j * 4;

    if (group == 0) {
        // ===== lo: 5x5 dwconv, scatter-accumulate (8 raw rows read once) =====
        float w[25];
#pragma unroll
        for (int i = 0; i < 25; i++) w[i] = s_w[i];
        float acc[4][4];
#pragma unroll
        for (int o = 0; o < 4; o++)
#pragma unroll
            for (int p = 0; p < 4; p++) acc[o][p] = 0.f;
        const float4* qb = s_raw + j;
        // raw rows gy0-2..gy0+5 -> slots rc*4+2 .. rc*4+9
#pragma unroll
        for (int rrow = 0; rrow < 8; rrow++) {
            float c[12];
            ld12(qb + (rc * 4 + 2 + rrow) * QS, c);
#pragma unroll
            for (int o = 0; o < 4; o++) {
                int kr = rrow - o;
                if (kr >= 0 && kr < 5) {
#pragma unroll
                    for (int kc = 0; kc < 5; kc++) {
                        float wv = w[kr * 5 + kc];
#pragma unroll
                        for (int p = 0; p < 4; p++)
                            acc[o][p] = fmaf(wv, c[p + 2 + kc], acc[o][p]);
                    }
                }
            }
        }
#pragma unroll
        for (int o = 0; o < 4; o++) {
            float4 ov;
            ov.x = bn_silu(acc[o][0], inv, shft);
            ov.y = bn_silu(acc[o][1], inv, shft);
            ov.z = bn_silu(acc[o][2], inv, shft);
            ov.w = bn_silu(acc[o][3], inv, shft);
            *(float4*)(outp + (size_t)(gy0 + o) * Wc) = ov;
        }
        return;
    }

    float w[9];
#pragma unroll
    for (int i = 0; i < 9; i++) w[i] = s_w[i];
    float icx3[4];
#pragma unroll
    for (int p = 0; p < 4; p++) icx3[p] = rcnt0(4 * j + p, 1);

    if (group == 1) {
        // ===== mf: vertical 3+7 sums (window in regs) =====
        for (int idx = t; idx < 6 * NQ; idx += 256) {
            int chunk = idx / NQ;
            int q = idx - chunk * NQ;
            int vr0 = chunk * 3;
            const float4* col = s_raw + q;
            float4 r0 = col[(vr0+0)*QS], r1 = col[(vr0+1)*QS], r2 = col[(vr0+2)*QS],
                   r3 = col[(vr0+3)*QS], r4 = col[(vr0+4)*QS], r5 = col[(vr0+5)*QS],
                   r6 = col[(vr0+6)*QS];
            float4 s3 = f4add(f4add(r2, r3), r4);
            float4 s7 = f4add(f4add(f4add(r0, r1), f4add(r5, r6)), s3);
            s_a[(vr0+0)*QS + q] = s3;  s_b[(vr0+0)*QS + q] = s7;
            float4 r7 = col[(vr0+7)*QS];
            s3 = f4add(s3, f4sub(r5, r2));  s7 = f4add(s7, f4sub(r7, r0));
            s_a[(vr0+1)*QS + q] = s3;  s_b[(vr0+1)*QS + q] = s7;
            float4 r8 = col[(vr0+8)*QS];
            s3 = f4add(s3, f4sub(r6, r3));  s7 = f4add(s7, f4sub(r8, r1));
            s_a[(vr0+2)*QS + q] = s3;  s_b[(vr0+2)*QS + q] = s7;
        }
        __syncthreads();

        // ===== band-pass rows into s_raw slots 0..17 (edge quads keep raw zeros) =====
        float icx7[4];
#pragma unroll
        for (int p = 0; p < 4; p++) icx7[p] = rcnt0(4 * j + p, 3);
        const int q = j + 1;
        for (int vr = rc; vr < VRS; vr += 4) {
            int g = rowBase + vr - 1;
            float iy3 = rcnt0(g, 1), iy7 = rcnt0(g, 3);
            float a[12], bb[12];
            ld12(s_a + vr * QS + j, a);
            ld12(s_b + vr * QS + j, bb);
            float h3_0 = a[3] + a[4] + a[5];
            float h3_1 = h3_0 + a[6] - a[3];
            float h3_2 = h3_1 + a[7] - a[4];
            float h3_3 = h3_2 + a[8] - a[5];
            float h7_0 = bb[1]+bb[2]+bb[3]+bb[4]+bb[5]+bb[6]+bb[7];
            float h7_1 = h7_0 + bb[8]  - bb[1];
            float h7_2 = h7_1 + bb[9]  - bb[2];
            float h7_3 = h7_2 + bb[10] - bb[3];
            float4 o;
            o.x = h3_0 * (icx3[0] * iy3) - h7_0 * (icx7[0] * iy7);
            o.y = h3_1 * (icx3[1] * iy3) - h7_1 * (icx7[1] * iy7);
            o.z = h3_2 * (icx3[2] * iy3) - h7_2 * (icx7[2] * iy7);
            o.w = h3_3 * (icx3[3] * iy3) - h7_3 * (icx7[3] * iy7);
            s_raw[vr * QS + q] = o;
        }
        __syncthreads();
        conv3_scatter(s_raw + j, rc * 4, w, inv, shft, outp, gy0);
        return;
    }

    // ===== hf: vertical 3-sums only =====
    for (int idx = t; idx < 6 * NQ; idx += 256) {
        int chunk = idx / NQ;
        int q = idx - chunk * NQ;
        int vr0 = chunk * 3;
        const float4* col = s_raw + q;
        float4 r2 = col[(vr0+2)*QS], r3 = col[(vr0+3)*QS], r4 = col[(vr0+4)*QS],
               r5 = col[(vr0+5)*QS], r6 = col[(vr0+6)*QS];
        float4 s3 = f4add(f4add(r2, r3), r4);
        s_a[(vr0+0)*QS + q] = s3;
        s3 = f4add(s3, f4sub(r5, r2));
        s_a[(vr0+1)*QS + q] = s3;
        s3 = f4add(s3, f4sub(r6, r3));
        s_a[(vr0+2)*QS + q] = s3;
    }
    // zero hp buffer edge quads (q=0, q=65) for conv halo
    if (t < 2 * VRS) {
        int vr = t % VRS;
        int qe = (t < VRS) ? 0 : 65;
        s_b[vr * QS + qe] = make_float4(0.f, 0.f, 0.f, 0.f);
    }
    __syncthreads();

    // ===== high-pass rows into s_b slots 0..17 =====
    {
        const int q = j + 1;
        for (int vr = rc; vr < VRS; vr += 4) {
            int g = rowBase + vr - 1;
            float iy3 = rcnt0(g, 1);
            float a[12];
            ld12(s_a + vr * QS + j, a);
            float4 rawv = s_raw[(vr + 3) * QS + q];   // raw row g
            float h3_0 = a[3] + a[4] + a[5];
            float h3_1 = h3_0 + a[6] - a[3];
            float h3_2 = h3_1 + a[7] - a[4];
            float h3_3 = h3_2 + a[8] - a[5];
            float4 o;
            o.x = rawv.x - h3_0 * (icx3[0] * iy3);
            o.y = rawv.y - h3_1 * (icx3[1] * iy3);
            o.z = rawv.z - h3_2 * (icx3[2] * iy3);
            o.w = rawv.w - h3_3 * (icx3[3] * iy3);
            s_b[vr * QS + q] = o;
        }
    }
    __syncthreads();
    conv3_scatter(s_b + j, rc * 4, w, inv, shft, outp, gy0);
}

extern "C" void kernel_launch(void* const* d_in, const int* in_sizes, int n_in,
                              void* d_out, int out_size) {
    (void)in_sizes; (void)n_in; (void)out_size;
    cudaFuncSetAttribute(trifreq_kernel,
                         cudaFuncAttributeMaxDynamicSharedMemorySize, SMEM_BYTES);
    dim3 grid(Hc / TH, Cc, Bc);
    dim3 block(256);
    trifreq_kernel<<<grid, block, SMEM_BYTES>>>(
        (const float*)d_in[0], (const float*)d_in[1], (const float*)d_in[2],
        (const float*)d_in[3], (const float*)d_in[4], (const float*)d_in[5],
        (const float*)d_in[6], (const float*)d_in[7], (float*)d_out);
}